// round 1
// baseline (speedup 1.0000x reference)
#include <cuda_runtime.h>
#include <cstdint>

#define N_NODES 50000
#define N_EDGES 800000
#define DIM     128
#define LAYERS  5

// ---------------- scratch (no allocation allowed) ----------------
__device__ float g_h[2][N_NODES * DIM];   // ping-pong hidden buffers
__device__ float g_agg[N_NODES * DIM];    // aggregation buffer
__device__ float g_deg_out[N_NODES];
__device__ float g_deg_in[N_NODES];
__device__ float g_norm_src[N_NODES];
__device__ float g_norm_dst[N_NODES];

// ---------------- degree / norm computation ----------------
__global__ void zero_deg_kernel() {
    int i = blockIdx.x * blockDim.x + threadIdx.x;
    if (i < N_NODES) { g_deg_out[i] = 0.0f; g_deg_in[i] = 0.0f; }
}

__global__ void count_deg_kernel(const int* __restrict__ src,
                                 const int* __restrict__ dst) {
    int e = blockIdx.x * blockDim.x + threadIdx.x;
    if (e < N_EDGES) {
        atomicAdd(&g_deg_out[src[e]], 1.0f);
        atomicAdd(&g_deg_in[dst[e]], 1.0f);
    }
}

__global__ void finalize_norm_kernel() {
    int i = blockIdx.x * blockDim.x + threadIdx.x;
    if (i < N_NODES) {
        g_norm_src[i] = rsqrtf(fmaxf(g_deg_out[i], 1.0f));
        g_norm_dst[i] = rsqrtf(fmaxf(g_deg_in[i], 1.0f));
    }
}

// ---------------- zero agg ----------------
__global__ void zero_agg_kernel() {
    int i = blockIdx.x * blockDim.x + threadIdx.x;
    const int total4 = N_NODES * DIM / 4;
    if (i < total4) {
        ((float4*)g_agg)[i] = make_float4(0.f, 0.f, 0.f, 0.f);
    }
}

// ---------------- SpMM: one warp per edge ----------------
// agg[dst] += h[src] * norm_src[src]
__global__ void spmm_kernel(const float* __restrict__ feat,
                            const int* __restrict__ src,
                            const int* __restrict__ dst,
                            int in_sel) {
    int gtid = blockIdx.x * blockDim.x + threadIdx.x;
    int e = gtid >> 5;
    int lane = threadIdx.x & 31;
    if (e >= N_EDGES) return;

    const float* __restrict__ h = (in_sel < 0) ? feat : g_h[in_sel];

    int s = src[e];
    int d = dst[e];
    float ns = g_norm_src[s];

    const float4* hrow = (const float4*)(h + (size_t)s * DIM);
    float* arow = g_agg + (size_t)d * DIM;

    float4 v = hrow[lane];          // DIM=128 -> 32 float4 per row, 1 per lane
    int c = lane * 4;
    atomicAdd(arow + c + 0, v.x * ns);
    atomicAdd(arow + c + 1, v.y * ns);
    atomicAdd(arow + c + 2, v.z * ns);
    atomicAdd(arow + c + 3, v.w * ns);
}

// ---------------- GEMM: out = relu((agg * norm_dst) @ W + b) ----------------
// Tile: BM=128, BN=128, BK=16. 256 threads (16x16), 8x8 outputs per thread.
__global__ __launch_bounds__(256, 2)
void gemm_relu_kernel(const float* __restrict__ Wl,
                      const float* __restrict__ bl,
                      float* __restrict__ ext_out,
                      int out_sel) {
    float* __restrict__ out = (out_sel < 0) ? ext_out : g_h[out_sel];

    __shared__ float As[16][128];   // k-major A tile (transposed on store)
    __shared__ float Bs[16][128];   // k-major W tile

    const int tid = threadIdx.x;
    const int tx = tid & 15;        // output column group
    const int ty = tid >> 4;        // output row group
    const int rowBase = blockIdx.x * 128;

    float acc[8][8];
    #pragma unroll
    for (int i = 0; i < 8; i++)
        #pragma unroll
        for (int j = 0; j < 8; j++) acc[i][j] = 0.0f;

    for (int kb = 0; kb < DIM; kb += 16) {
        // --- load A tile (128 rows x 16 k), scaled by norm_dst, transposed into As ---
        #pragma unroll
        for (int it = 0; it < 2; it++) {
            int f = tid + it * 256;          // float4 index, 0..511
            int r  = f >> 2;                 // row within tile, 0..127
            int c4 = f & 3;                  // which float4 within 16 k's
            int grow = rowBase + r;
            float4 v = make_float4(0.f, 0.f, 0.f, 0.f);
            if (grow < N_NODES) {
                v = *(const float4*)(&g_agg[(size_t)grow * DIM + kb + c4 * 4]);
                float nd = g_norm_dst[grow];
                v.x *= nd; v.y *= nd; v.z *= nd; v.w *= nd;
            }
            As[c4 * 4 + 0][r] = v.x;
            As[c4 * 4 + 1][r] = v.y;
            As[c4 * 4 + 2][r] = v.z;
            As[c4 * 4 + 3][r] = v.w;

            // --- load B tile (16 k x 128 n), coalesced float4 ---
            int kr = f >> 5;                 // 0..15
            int c  = (f & 31) * 4;           // 0..124
            *(float4*)&Bs[kr][c] =
                *(const float4*)(&Wl[(size_t)(kb + kr) * DIM + c]);
        }
        __syncthreads();

        #pragma unroll
        for (int kk = 0; kk < 16; kk++) {
            float a[8], bv[8];
            #pragma unroll
            for (int i = 0; i < 8; i++) a[i] = As[kk][ty * 8 + i];
            #pragma unroll
            for (int j = 0; j < 8; j++) bv[j] = Bs[kk][tx * 8 + j];
            #pragma unroll
            for (int i = 0; i < 8; i++)
                #pragma unroll
                for (int j = 0; j < 8; j++)
                    acc[i][j] += a[i] * bv[j];
        }
        __syncthreads();
    }

    // --- epilogue: bias + relu ---
    float bias[8];
    #pragma unroll
    for (int j = 0; j < 8; j++) bias[j] = bl[tx * 8 + j];

    #pragma unroll
    for (int i = 0; i < 8; i++) {
        int grow = rowBase + ty * 8 + i;
        if (grow < N_NODES) {
            float4 o0, o1;
            o0.x = fmaxf(acc[i][0] + bias[0], 0.f);
            o0.y = fmaxf(acc[i][1] + bias[1], 0.f);
            o0.z = fmaxf(acc[i][2] + bias[2], 0.f);
            o0.w = fmaxf(acc[i][3] + bias[3], 0.f);
            o1.x = fmaxf(acc[i][4] + bias[4], 0.f);
            o1.y = fmaxf(acc[i][5] + bias[5], 0.f);
            o1.z = fmaxf(acc[i][6] + bias[6], 0.f);
            o1.w = fmaxf(acc[i][7] + bias[7], 0.f);
            float* orow = out + (size_t)grow * DIM + tx * 8;
            *(float4*)(orow)     = o0;
            *(float4*)(orow + 4) = o1;
        }
    }
}

// ---------------- launch ----------------
extern "C" void kernel_launch(void* const* d_in, const int* in_sizes, int n_in,
                              void* d_out, int out_size) {
    const float* feat = (const float*)d_in[0];   // [N, D]
    const int*   src  = (const int*)d_in[1];     // [E]
    const int*   dst  = (const int*)d_in[2];     // [E]
    const float* W    = (const float*)d_in[3];   // [L, D, D]
    const float* b    = (const float*)d_in[4];   // [L, D]
    float* out = (float*)d_out;                  // [N, D]

    (void)in_sizes; (void)n_in; (void)out_size;

    // degrees + norms
    zero_deg_kernel<<<(N_NODES + 255) / 256, 256>>>();
    count_deg_kernel<<<(N_EDGES + 255) / 256, 256>>>(src, dst);
    finalize_norm_kernel<<<(N_NODES + 255) / 256, 256>>>();

    const int zero_blocks = (N_NODES * DIM / 4 + 255) / 256;
    const int spmm_blocks = (N_EDGES * 32 + 255) / 256;   // warp per edge
    const int gemm_blocks = (N_NODES + 127) / 128;

    for (int l = 0; l < LAYERS; l++) {
        int in_sel  = (l == 0) ? -1 : ((l - 1) & 1);
        int out_sel = (l == LAYERS - 1) ? -1 : (l & 1);

        zero_agg_kernel<<<zero_blocks, 256>>>();
        spmm_kernel<<<spmm_blocks, 256>>>(feat, src, dst, in_sel);
        gemm_relu_kernel<<<gemm_blocks, 256>>>(
            W + (size_t)l * DIM * DIM, b + (size_t)l * DIM, out, out_sel);
    }
}

// round 2
// speedup vs baseline: 2.6567x; 2.6567x over previous
#include <cuda_runtime.h>
#include <cstdint>

#define N_NODES 50000
#define N_EDGES 800000
#define DIM     128
#define LAYERS  5

// ---------------- scratch (no allocation allowed) ----------------
__device__ float g_h[2][N_NODES * DIM];   // ping-pong hidden buffers
__device__ float g_agg[N_NODES * DIM];    // aggregation buffer
__device__ int   g_deg_out[N_NODES];
__device__ int   g_deg_in[N_NODES];
__device__ float g_norm_src[N_NODES];
__device__ float g_norm_dst[N_NODES];
__device__ int   g_row_ptr[N_NODES + 1];
__device__ int   g_cursor[N_NODES];
__device__ int   g_csr_src[N_EDGES];
__device__ float g_csr_w[N_EDGES];

// ---------------- degree / norm computation ----------------
__global__ void zero_deg_kernel() {
    int i = blockIdx.x * blockDim.x + threadIdx.x;
    if (i < N_NODES) { g_deg_out[i] = 0; g_deg_in[i] = 0; }
}

__global__ void count_deg_kernel(const int* __restrict__ src,
                                 const int* __restrict__ dst) {
    int e = blockIdx.x * blockDim.x + threadIdx.x;
    if (e < N_EDGES) {
        atomicAdd(&g_deg_out[src[e]], 1);
        atomicAdd(&g_deg_in[dst[e]], 1);
    }
}

__global__ void finalize_norm_kernel() {
    int i = blockIdx.x * blockDim.x + threadIdx.x;
    if (i < N_NODES) {
        g_norm_src[i] = rsqrtf(fmaxf((float)g_deg_out[i], 1.0f));
        g_norm_dst[i] = rsqrtf(fmaxf((float)g_deg_in[i], 1.0f));
    }
}

// ---------------- single-block exclusive scan of deg_in -> row_ptr ----------------
__global__ __launch_bounds__(1024)
void scan_rowptr_kernel() {
    __shared__ int warp_sums[32];
    const int T = 1024;
    const int CH = (N_NODES + T - 1) / T;   // 49
    int tid  = threadIdx.x;
    int lane = tid & 31;
    int wid  = tid >> 5;
    int base = tid * CH;

    // pass 1: local chunk sum
    int local = 0;
    for (int j = 0; j < CH; j++) {
        int idx = base + j;
        if (idx < N_NODES) local += g_deg_in[idx];
    }

    // inclusive warp scan
    int v = local;
    #pragma unroll
    for (int o = 1; o < 32; o <<= 1) {
        int n = __shfl_up_sync(0xFFFFFFFFu, v, o);
        if (lane >= o) v += n;
    }
    if (lane == 31) warp_sums[wid] = v;
    __syncthreads();
    if (wid == 0) {
        int s = warp_sums[lane];
        #pragma unroll
        for (int o = 1; o < 32; o <<= 1) {
            int n = __shfl_up_sync(0xFFFFFFFFu, s, o);
            if (lane >= o) s += n;
        }
        warp_sums[lane] = s;   // inclusive over warps
    }
    __syncthreads();
    int excl = v - local + (wid > 0 ? warp_sums[wid - 1] : 0);

    // pass 2: write exclusive row offsets + cursors
    int run = excl;
    for (int j = 0; j < CH; j++) {
        int idx = base + j;
        if (idx < N_NODES) {
            g_row_ptr[idx] = run;
            g_cursor[idx]  = run;
            run += g_deg_in[idx];
        }
    }
    if (tid == T - 1) g_row_ptr[N_NODES] = run;   // == N_EDGES
}

// ---------------- scatter edges into CSR with fused edge weight ----------------
__global__ void scatter_edges_kernel(const int* __restrict__ src,
                                     const int* __restrict__ dst) {
    int e = blockIdx.x * blockDim.x + threadIdx.x;
    if (e < N_EDGES) {
        int s = src[e];
        int d = dst[e];
        int pos = atomicAdd(&g_cursor[d], 1);
        g_csr_src[pos] = s;
        g_csr_w[pos]   = g_norm_src[s] * g_norm_dst[d];
    }
}

// ---------------- SpMM (CSR gather): one warp per dst node ----------------
// agg[d] = sum_{edges into d} w[e] * h[src[e]]   (norms pre-folded into w)
__global__ __launch_bounds__(256)
void spmm_csr_kernel(const float* __restrict__ feat, int in_sel) {
    int node = blockIdx.x * (blockDim.x >> 5) + (threadIdx.x >> 5);
    if (node >= N_NODES) return;
    int lane = threadIdx.x & 31;

    const float* __restrict__ h = (in_sel < 0) ? feat : g_h[in_sel];

    int beg = g_row_ptr[node];
    int end = g_row_ptr[node + 1];

    float ax = 0.f, ay = 0.f, az = 0.f, aw = 0.f;
    float bx = 0.f, by = 0.f, bz = 0.f, bw = 0.f;

    int i = beg;
    for (; i + 1 < end; i += 2) {
        int   s0 = g_csr_src[i];
        int   s1 = g_csr_src[i + 1];
        float w0 = g_csr_w[i];
        float w1 = g_csr_w[i + 1];
        float4 v0 = ((const float4*)(h + (size_t)s0 * DIM))[lane];
        float4 v1 = ((const float4*)(h + (size_t)s1 * DIM))[lane];
        ax += v0.x * w0; ay += v0.y * w0; az += v0.z * w0; aw += v0.w * w0;
        bx += v1.x * w1; by += v1.y * w1; bz += v1.z * w1; bw += v1.w * w1;
    }
    if (i < end) {
        int   s0 = g_csr_src[i];
        float w0 = g_csr_w[i];
        float4 v0 = ((const float4*)(h + (size_t)s0 * DIM))[lane];
        ax += v0.x * w0; ay += v0.y * w0; az += v0.z * w0; aw += v0.w * w0;
    }

    float4 o;
    o.x = ax + bx; o.y = ay + by; o.z = az + bz; o.w = aw + bw;
    ((float4*)(g_agg + (size_t)node * DIM))[lane] = o;
}

// ---------------- GEMM: out = relu(agg @ W + b) ----------------
// (norm_dst already folded into edge weights)
// Tile: BM=128, BN=128, BK=16. 256 threads, 8x8 outputs per thread.
__global__ __launch_bounds__(256, 2)
void gemm_relu_kernel(const float* __restrict__ Wl,
                      const float* __restrict__ bl,
                      float* __restrict__ ext_out,
                      int out_sel) {
    float* __restrict__ out = (out_sel < 0) ? ext_out : g_h[out_sel];

    __shared__ float As[16][128];   // k-major A tile (transposed on store)
    __shared__ float Bs[16][128];   // k-major W tile

    const int tid = threadIdx.x;
    const int tx = tid & 15;
    const int ty = tid >> 4;
    const int rowBase = blockIdx.x * 128;

    float acc[8][8];
    #pragma unroll
    for (int i = 0; i < 8; i++)
        #pragma unroll
        for (int j = 0; j < 8; j++) acc[i][j] = 0.0f;

    for (int kb = 0; kb < DIM; kb += 16) {
        #pragma unroll
        for (int it = 0; it < 2; it++) {
            int f = tid + it * 256;          // float4 index, 0..511
            int r  = f >> 2;
            int c4 = f & 3;
            int grow = rowBase + r;
            float4 v = make_float4(0.f, 0.f, 0.f, 0.f);
            if (grow < N_NODES)
                v = *(const float4*)(&g_agg[(size_t)grow * DIM + kb + c4 * 4]);
            As[c4 * 4 + 0][r] = v.x;
            As[c4 * 4 + 1][r] = v.y;
            As[c4 * 4 + 2][r] = v.z;
            As[c4 * 4 + 3][r] = v.w;

            int kr = f >> 5;
            int c  = (f & 31) * 4;
            *(float4*)&Bs[kr][c] =
                *(const float4*)(&Wl[(size_t)(kb + kr) * DIM + c]);
        }
        __syncthreads();

        #pragma unroll
        for (int kk = 0; kk < 16; kk++) {
            float a[8], bv[8];
            #pragma unroll
            for (int i = 0; i < 8; i++) a[i] = As[kk][ty * 8 + i];
            #pragma unroll
            for (int j = 0; j < 8; j++) bv[j] = Bs[kk][tx * 8 + j];
            #pragma unroll
            for (int i = 0; i < 8; i++)
                #pragma unroll
                for (int j = 0; j < 8; j++)
                    acc[i][j] += a[i] * bv[j];
        }
        __syncthreads();
    }

    float bias[8];
    #pragma unroll
    for (int j = 0; j < 8; j++) bias[j] = bl[tx * 8 + j];

    #pragma unroll
    for (int i = 0; i < 8; i++) {
        int grow = rowBase + ty * 8 + i;
        if (grow < N_NODES) {
            float4 o0, o1;
            o0.x = fmaxf(acc[i][0] + bias[0], 0.f);
            o0.y = fmaxf(acc[i][1] + bias[1], 0.f);
            o0.z = fmaxf(acc[i][2] + bias[2], 0.f);
            o0.w = fmaxf(acc[i][3] + bias[3], 0.f);
            o1.x = fmaxf(acc[i][4] + bias[4], 0.f);
            o1.y = fmaxf(acc[i][5] + bias[5], 0.f);
            o1.z = fmaxf(acc[i][6] + bias[6], 0.f);
            o1.w = fmaxf(acc[i][7] + bias[7], 0.f);
            float* orow = out + (size_t)grow * DIM + tx * 8;
            *(float4*)(orow)     = o0;
            *(float4*)(orow + 4) = o1;
        }
    }
}

// ---------------- launch ----------------
extern "C" void kernel_launch(void* const* d_in, const int* in_sizes, int n_in,
                              void* d_out, int out_size) {
    const float* feat = (const float*)d_in[0];   // [N, D]
    const int*   src  = (const int*)d_in[1];     // [E]
    const int*   dst  = (const int*)d_in[2];     // [E]
    const float* W    = (const float*)d_in[3];   // [L, D, D]
    const float* b    = (const float*)d_in[4];   // [L, D]
    float* out = (float*)d_out;                  // [N, D]

    (void)in_sizes; (void)n_in; (void)out_size;

    // ---- one-time CSR build (per launch, graph-capturable) ----
    zero_deg_kernel<<<(N_NODES + 255) / 256, 256>>>();
    count_deg_kernel<<<(N_EDGES + 255) / 256, 256>>>(src, dst);
    finalize_norm_kernel<<<(N_NODES + 255) / 256, 256>>>();
    scan_rowptr_kernel<<<1, 1024>>>();
    scatter_edges_kernel<<<(N_EDGES + 255) / 256, 256>>>(src, dst);

    const int warps_per_block = 256 / 32;
    const int spmm_blocks = (N_NODES + warps_per_block - 1) / warps_per_block;
    const int gemm_blocks = (N_NODES + 127) / 128;

    for (int l = 0; l < LAYERS; l++) {
        int in_sel  = (l == 0) ? -1 : ((l - 1) & 1);
        int out_sel = (l == LAYERS - 1) ? -1 : (l & 1);

        spmm_csr_kernel<<<spmm_blocks, 256>>>(feat, in_sel);
        gemm_relu_kernel<<<gemm_blocks, 256>>>(
            W + (size_t)l * DIM * DIM, b + (size_t)l * DIM, out, out_sel);
    }
}

// round 3
// speedup vs baseline: 3.0982x; 1.1662x over previous
#include <cuda_runtime.h>
#include <cstdint>

#define N_NODES 50000
#define N_EDGES 800000
#define DIM     128
#define LAYERS  5

#define SCAN_CHUNK  256
#define SCAN_BLOCKS ((N_NODES + SCAN_CHUNK - 1) / SCAN_CHUNK)   // 196

// ---------------- scratch (no allocation allowed) ----------------
__device__ float g_h[2][N_NODES * DIM];   // ping-pong hidden buffers
__device__ float g_agg[N_NODES * DIM];    // aggregation buffer
__device__ int   g_deg_out[N_NODES];
__device__ int   g_deg_in[N_NODES];
__device__ float g_norm_src[N_NODES];
__device__ float g_norm_dst[N_NODES];
__device__ int   g_row_ptr[N_NODES + 1];
__device__ int   g_cursor[N_NODES];
__device__ int   g_csr_src[N_EDGES];
__device__ float g_csr_w[N_EDGES];
__device__ int   g_partial[SCAN_BLOCKS];

// ---------------- degree / norm computation ----------------
__global__ void zero_deg_kernel() {
    int i = blockIdx.x * blockDim.x + threadIdx.x;
    if (i < N_NODES) { g_deg_out[i] = 0; g_deg_in[i] = 0; }
}

__global__ void count_deg_kernel(const int* __restrict__ src,
                                 const int* __restrict__ dst) {
    int e = blockIdx.x * blockDim.x + threadIdx.x;
    if (e < N_EDGES) {
        atomicAdd(&g_deg_out[src[e]], 1);
        atomicAdd(&g_deg_in[dst[e]], 1);
    }
}

__global__ void finalize_norm_kernel() {
    int i = blockIdx.x * blockDim.x + threadIdx.x;
    if (i < N_NODES) {
        g_norm_src[i] = rsqrtf(fmaxf((float)g_deg_out[i], 1.0f));
        g_norm_dst[i] = rsqrtf(fmaxf((float)g_deg_in[i], 1.0f));
    }
}

// ---------------- decoupled scan: phase A (per-block sums) ----------------
__global__ __launch_bounds__(SCAN_CHUNK)
void scan_partial_kernel() {
    __shared__ int wsum[SCAN_CHUNK / 32];
    int tid  = threadIdx.x;
    int lane = tid & 31;
    int wid  = tid >> 5;
    int i = blockIdx.x * SCAN_CHUNK + tid;
    int v = (i < N_NODES) ? g_deg_in[i] : 0;
    #pragma unroll
    for (int o = 16; o > 0; o >>= 1) v += __shfl_down_sync(0xFFFFFFFFu, v, o);
    if (lane == 0) wsum[wid] = v;
    __syncthreads();
    if (tid == 0) {
        int s = 0;
        #pragma unroll
        for (int w = 0; w < SCAN_CHUNK / 32; w++) s += wsum[w];
        g_partial[blockIdx.x] = s;
    }
}

// ---------------- phase B (1 block: exclusive scan of partials) ----------------
__global__ __launch_bounds__(256)
void scan_offsets_kernel() {
    __shared__ int wsum[8];
    int tid  = threadIdx.x;
    int lane = tid & 31;
    int wid  = tid >> 5;
    int v = (tid < SCAN_BLOCKS) ? g_partial[tid] : 0;
    int orig = v;
    #pragma unroll
    for (int o = 1; o < 32; o <<= 1) {
        int n = __shfl_up_sync(0xFFFFFFFFu, v, o);
        if (lane >= o) v += n;
    }
    if (lane == 31) wsum[wid] = v;
    __syncthreads();
    if (wid == 0 && lane < 8) {
        int s = wsum[lane];
        #pragma unroll
        for (int o = 1; o < 8; o <<= 1) {
            int n = __shfl_up_sync(0xFFu, s, o);
            if (lane >= o) s += n;
        }
        wsum[lane] = s;
    }
    __syncthreads();
    int excl = v - orig + (wid > 0 ? wsum[wid - 1] : 0);
    if (tid < SCAN_BLOCKS) g_partial[tid] = excl;
}

// ---------------- phase C (per-block scan + write row_ptr / cursor) ----------------
__global__ __launch_bounds__(SCAN_CHUNK)
void scan_write_kernel() {
    __shared__ int wsum[SCAN_CHUNK / 32];
    int tid  = threadIdx.x;
    int lane = tid & 31;
    int wid  = tid >> 5;
    int i = blockIdx.x * SCAN_CHUNK + tid;
    int orig = (i < N_NODES) ? g_deg_in[i] : 0;
    int v = orig;
    #pragma unroll
    for (int o = 1; o < 32; o <<= 1) {
        int n = __shfl_up_sync(0xFFFFFFFFu, v, o);
        if (lane >= o) v += n;
    }
    if (lane == 31) wsum[wid] = v;
    __syncthreads();
    if (wid == 0 && lane < SCAN_CHUNK / 32) {
        int s = wsum[lane];
        #pragma unroll
        for (int o = 1; o < SCAN_CHUNK / 32; o <<= 1) {
            int n = __shfl_up_sync(0xFFu, s, o);
            if (lane >= o) s += n;
        }
        wsum[lane] = s;
    }
    __syncthreads();
    int excl = v - orig + (wid > 0 ? wsum[wid - 1] : 0) + g_partial[blockIdx.x];
    if (i < N_NODES) {
        g_row_ptr[i] = excl;
        g_cursor[i]  = excl;
        if (i == N_NODES - 1) g_row_ptr[N_NODES] = excl + orig;  // == N_EDGES
    }
}

// ---------------- scatter edges into CSR with fused edge weight ----------------
__global__ void scatter_edges_kernel(const int* __restrict__ src,
                                     const int* __restrict__ dst) {
    int e = blockIdx.x * blockDim.x + threadIdx.x;
    if (e < N_EDGES) {
        int s = src[e];
        int d = dst[e];
        int pos = atomicAdd(&g_cursor[d], 1);
        g_csr_src[pos] = s;
        g_csr_w[pos]   = g_norm_src[s] * g_norm_dst[d];
    }
}

// ---------------- SpMM (CSR gather): one warp per dst node ----------------
// agg[d] = sum_{edges into d} w[e] * h[src[e]]   (norms pre-folded into w)
__global__ __launch_bounds__(256)
void spmm_csr_kernel(const float* __restrict__ feat, int in_sel) {
    int node = blockIdx.x * (blockDim.x >> 5) + (threadIdx.x >> 5);
    if (node >= N_NODES) return;
    int lane = threadIdx.x & 31;

    const float* __restrict__ h = (in_sel < 0) ? feat : g_h[in_sel];

    int beg = g_row_ptr[node];
    int end = g_row_ptr[node + 1];

    float ax = 0.f, ay = 0.f, az = 0.f, aw = 0.f;
    float bx = 0.f, by = 0.f, bz = 0.f, bw = 0.f;

    int i = beg;
    for (; i + 1 < end; i += 2) {
        int   s0 = g_csr_src[i];
        int   s1 = g_csr_src[i + 1];
        float w0 = g_csr_w[i];
        float w1 = g_csr_w[i + 1];
        float4 v0 = ((const float4*)(h + (size_t)s0 * DIM))[lane];
        float4 v1 = ((const float4*)(h + (size_t)s1 * DIM))[lane];
        ax += v0.x * w0; ay += v0.y * w0; az += v0.z * w0; aw += v0.w * w0;
        bx += v1.x * w1; by += v1.y * w1; bz += v1.z * w1; bw += v1.w * w1;
    }
    if (i < end) {
        int   s0 = g_csr_src[i];
        float w0 = g_csr_w[i];
        float4 v0 = ((const float4*)(h + (size_t)s0 * DIM))[lane];
        ax += v0.x * w0; ay += v0.y * w0; az += v0.z * w0; aw += v0.w * w0;
    }

    float4 o;
    o.x = ax + bx; o.y = ay + by; o.z = az + bz; o.w = aw + bw;
    ((float4*)(g_agg + (size_t)node * DIM))[lane] = o;
}

// ---------------- GEMM: out = relu(agg @ W + b) ----------------
// Tile: BM=128, BN=128, BK=16. 256 threads, 8x8 outputs per thread.
__global__ __launch_bounds__(256, 2)
void gemm_relu_kernel(const float* __restrict__ Wl,
                      const float* __restrict__ bl,
                      float* __restrict__ ext_out,
                      int out_sel) {
    float* __restrict__ out = (out_sel < 0) ? ext_out : g_h[out_sel];

    __shared__ float As[16][128];   // k-major A tile (transposed on store)
    __shared__ float Bs[16][128];   // k-major W tile

    const int tid = threadIdx.x;
    const int tx = tid & 15;
    const int ty = tid >> 4;
    const int rowBase = blockIdx.x * 128;

    float acc[8][8];
    #pragma unroll
    for (int i = 0; i < 8; i++)
        #pragma unroll
        for (int j = 0; j < 8; j++) acc[i][j] = 0.0f;

    for (int kb = 0; kb < DIM; kb += 16) {
        #pragma unroll
        for (int it = 0; it < 2; it++) {
            int f = tid + it * 256;          // float4 index, 0..511
            int r  = f >> 2;
            int c4 = f & 3;
            int grow = rowBase + r;
            float4 v = make_float4(0.f, 0.f, 0.f, 0.f);
            if (grow < N_NODES)
                v = *(const float4*)(&g_agg[(size_t)grow * DIM + kb + c4 * 4]);
            As[c4 * 4 + 0][r] = v.x;
            As[c4 * 4 + 1][r] = v.y;
            As[c4 * 4 + 2][r] = v.z;
            As[c4 * 4 + 3][r] = v.w;

            int kr = f >> 5;
            int c  = (f & 31) * 4;
            *(float4*)&Bs[kr][c] =
                *(const float4*)(&Wl[(size_t)(kb + kr) * DIM + c]);
        }
        __syncthreads();

        #pragma unroll
        for (int kk = 0; kk < 16; kk++) {
            float a[8], bv[8];
            #pragma unroll
            for (int i = 0; i < 8; i++) a[i] = As[kk][ty * 8 + i];
            #pragma unroll
            for (int j = 0; j < 8; j++) bv[j] = Bs[kk][tx * 8 + j];
            #pragma unroll
            for (int i = 0; i < 8; i++)
                #pragma unroll
                for (int j = 0; j < 8; j++)
                    acc[i][j] += a[i] * bv[j];
        }
        __syncthreads();
    }

    float bias[8];
    #pragma unroll
    for (int j = 0; j < 8; j++) bias[j] = bl[tx * 8 + j];

    #pragma unroll
    for (int i = 0; i < 8; i++) {
        int grow = rowBase + ty * 8 + i;
        if (grow < N_NODES) {
            float4 o0, o1;
            o0.x = fmaxf(acc[i][0] + bias[0], 0.f);
            o0.y = fmaxf(acc[i][1] + bias[1], 0.f);
            o0.z = fmaxf(acc[i][2] + bias[2], 0.f);
            o0.w = fmaxf(acc[i][3] + bias[3], 0.f);
            o1.x = fmaxf(acc[i][4] + bias[4], 0.f);
            o1.y = fmaxf(acc[i][5] + bias[5], 0.f);
            o1.z = fmaxf(acc[i][6] + bias[6], 0.f);
            o1.w = fmaxf(acc[i][7] + bias[7], 0.f);
            float* orow = out + (size_t)grow * DIM + tx * 8;
            *(float4*)(orow)     = o0;
            *(float4*)(orow + 4) = o1;
        }
    }
}

// ---------------- launch ----------------
extern "C" void kernel_launch(void* const* d_in, const int* in_sizes, int n_in,
                              void* d_out, int out_size) {
    const float* feat = (const float*)d_in[0];   // [N, D]
    const int*   src  = (const int*)d_in[1];     // [E]
    const int*   dst  = (const int*)d_in[2];     // [E]
    const float* W    = (const float*)d_in[3];   // [L, D, D]
    const float* b    = (const float*)d_in[4];   // [L, D]
    float* out = (float*)d_out;                  // [N, D]

    (void)in_sizes; (void)n_in; (void)out_size;

    // ---- one-time CSR build (per launch, graph-capturable) ----
    zero_deg_kernel<<<(N_NODES + 255) / 256, 256>>>();
    count_deg_kernel<<<(N_EDGES + 255) / 256, 256>>>(src, dst);
    finalize_norm_kernel<<<(N_NODES + 255) / 256, 256>>>();
    scan_partial_kernel<<<SCAN_BLOCKS, SCAN_CHUNK>>>();
    scan_offsets_kernel<<<1, 256>>>();
    scan_write_kernel<<<SCAN_BLOCKS, SCAN_CHUNK>>>();
    scatter_edges_kernel<<<(N_EDGES + 255) / 256, 256>>>(src, dst);

    const int warps_per_block = 256 / 32;
    const int spmm_blocks = (N_NODES + warps_per_block - 1) / warps_per_block;
    const int gemm_blocks = (N_NODES + 127) / 128;

    for (int l = 0; l < LAYERS; l++) {
        int in_sel  = (l == 0) ? -1 : ((l - 1) & 1);
        int out_sel = (l == LAYERS - 1) ? -1 : (l & 1);

        spmm_csr_kernel<<<spmm_blocks, 256>>>(feat, in_sel);
        gemm_relu_kernel<<<gemm_blocks, 256>>>(
            W + (size_t)l * DIM * DIM, b + (size_t)l * DIM, out, out_sel);
    }
}